// round 10
// baseline (speedup 1.0000x reference)
#include <cuda_runtime.h>
#include <math.h>

// Problem constants
static const int Bc  = 128;    // batch
static const int Tc  = 256;    // time steps
static const int Rc  = 1024;   // recurrent width

// ---------------------------------------------------------------------------
// Device scratch (no allocations allowed -> __device__ globals)
// ---------------------------------------------------------------------------
__device__ float g_x [32768 * 256];      // gathered embeddings, row = t*B + b
__device__ float g_xh[33554432];         // xh[t*B+b][r]  (x@Wh0x + bh0)
__device__ float g_xt[33554432];         // xt[t*B+b][r]  (x@Wt0x + bt0)
__device__ float g_s [2][128 * 1024];    // ping-pong state, row-major [b][r]
__device__ unsigned g_cnt = 0;           // grid barrier arrival counter
__device__ unsigned g_gen = 0;           // grid barrier generation

// 4-wide multiply-accumulate (function, NOT a macro: a macro parameter named
// `w` would capture the `.w` member token and break expansion).
static __device__ __forceinline__ void acc4(float& acc, const float4& a,
                                            const float4& b) {
    acc += a.x * b.x;
    acc += a.y * b.y;
    acc += a.z * b.z;
    acc += a.w * b.w;
}

// Software grid barrier for a co-resident 128-CTA persistent kernel.
// Writer-side __threadfence before arrive; reader-side __threadfence after
// release (gpu-scope fence -> CCTL.IVALL on sm_103a, invalidates L1D).
static __device__ __forceinline__ void gbar() {
    __threadfence();
    __syncthreads();
    if (threadIdx.x == 0) {
        unsigned g = *((volatile unsigned*)&g_gen);
        if (atomicAdd(&g_cnt, 1) == gridDim.x - 1) {
            g_cnt = 0;
            __threadfence();
            atomicAdd(&g_gen, 1);
        } else {
            while (*((volatile unsigned*)&g_gen) == g) { }
        }
    }
    __syncthreads();
    __threadfence();
}

// ---------------------------------------------------------------------------
// Zero the initial state
// ---------------------------------------------------------------------------
__global__ void zero_kernel() {
    int i = blockIdx.x * 256 + threadIdx.x;          // 32768 float4
    ((float4*)g_s[0])[i] = make_float4(0.f, 0.f, 0.f, 0.f);
}

// ---------------------------------------------------------------------------
// Embedding gather: g_x[t*B+b][0:256] = emb[ids[b*T+t]][0:256]
// ---------------------------------------------------------------------------
__global__ void gather_kernel(const int* __restrict__ ids,
                              const float* __restrict__ emb) {
    int idx = blockIdx.x * 256 + threadIdx.x;        // 32768 rows * 64 f4
    int row = idx >> 6;
    int c   = (idx & 63) << 2;
    int t = row >> 7;            // B = 128
    int b = row & 127;
    int id = ids[b * Tc + t];
    *(float4*)&g_x[(size_t)row * 256 + c] =
        *(const float4*)&emb[(size_t)id * 256 + c];
}

// ---------------------------------------------------------------------------
// Prologue dual GEMM: xh = x@Whx + bh ; xt = x@Wtx + bt
// A = g_x [32768 x 256], W [256 x 1024].  Tile [64m x 16n x 2gates],
// 256 threads, 8 acc/thread, KC=32, double-buffered smem.
// grid: (64 n-tiles, 512 m-tiles)
// ---------------------------------------------------------------------------
__global__ __launch_bounds__(256) void prologue_kernel(
    const float* __restrict__ Whx, const float* __restrict__ Wtx,
    const float* __restrict__ bh,  const float* __restrict__ bt) {
    __shared__ float sA [2][64 * 36];
    __shared__ float sWh[2][16 * 36];
    __shared__ float sWt[2][16 * 36];

    const int tid = threadIdx.x;
    const int tx  = tid & 7;          // colgroup 0..7
    const int ty  = tid >> 3;         // rowgroup 0..31
    const int n0  = blockIdx.x * 16;
    const int m0  = blockIdx.y * 64;
    const int LDA = 256, LDW = 1024;

    const int sm  = tid >> 3;               // 0..31
    const int sk4 = (tid & 7) * 4;          // 0,4,...,28
    const int wn  = tid & 15;               // 0..15
    const int wk  = tid >> 4;               // 0..15

    float aH[2][2] = {{0.f,0.f},{0.f,0.f}};
    float aT[2][2] = {{0.f,0.f},{0.f,0.f}};

    #pragma unroll
    for (int r = 0; r < 2; r++) {
        int m = sm + r * 32;
        *(float4*)&sA[0][m * 36 + sk4] =
            *(const float4*)&g_x[(size_t)(m0 + m) * LDA + sk4];
    }
    #pragma unroll
    for (int r = 0; r < 2; r++) {
        int kk = wk + r * 16;
        sWh[0][wn * 36 + kk] = Whx[(size_t)kk * LDW + n0 + wn];
        sWt[0][wn * 36 + kk] = Wtx[(size_t)kk * LDW + n0 + wn];
    }
    __syncthreads();

    const int NS = 256 / 32;     // 8 stages
    for (int st = 0; st < NS; st++) {
        const int cur = st & 1;
        float4 pA0, pA1; float pWh0, pWh1, pWt0, pWt1;
        if (st + 1 < NS) {
            int k0 = (st + 1) * 32;
            pA0 = *(const float4*)&g_x[(size_t)(m0 + sm     ) * LDA + k0 + sk4];
            pA1 = *(const float4*)&g_x[(size_t)(m0 + sm + 32) * LDA + k0 + sk4];
            pWh0 = Whx[(size_t)(k0 + wk     ) * LDW + n0 + wn];
            pWh1 = Whx[(size_t)(k0 + wk + 16) * LDW + n0 + wn];
            pWt0 = Wtx[(size_t)(k0 + wk     ) * LDW + n0 + wn];
            pWt1 = Wtx[(size_t)(k0 + wk + 16) * LDW + n0 + wn];
        }
        #pragma unroll
        for (int k4 = 0; k4 < 8; k4++) {
            float4 a0 = *(const float4*)&sA [cur][ ty       * 36 + k4 * 4];
            float4 a1 = *(const float4*)&sA [cur][(ty + 32) * 36 + k4 * 4];
            float4 h0 = *(const float4*)&sWh[cur][ tx       * 36 + k4 * 4];
            float4 h1 = *(const float4*)&sWh[cur][(tx + 8 ) * 36 + k4 * 4];
            float4 q0 = *(const float4*)&sWt[cur][ tx       * 36 + k4 * 4];
            float4 q1 = *(const float4*)&sWt[cur][(tx + 8 ) * 36 + k4 * 4];
            acc4(aH[0][0], a0, h0); acc4(aH[0][1], a0, h1);
            acc4(aH[1][0], a1, h0); acc4(aH[1][1], a1, h1);
            acc4(aT[0][0], a0, q0); acc4(aT[0][1], a0, q1);
            acc4(aT[1][0], a1, q0); acc4(aT[1][1], a1, q1);
        }
        if (st + 1 < NS) {
            int nb = cur ^ 1;
            *(float4*)&sA[nb][ sm       * 36 + sk4] = pA0;
            *(float4*)&sA[nb][(sm + 32) * 36 + sk4] = pA1;
            sWh[nb][wn * 36 + wk     ] = pWh0;
            sWh[nb][wn * 36 + wk + 16] = pWh1;
            sWt[nb][wn * 36 + wk     ] = pWt0;
            sWt[nb][wn * 36 + wk + 16] = pWt1;
        }
        __syncthreads();
    }

    #pragma unroll
    for (int r = 0; r < 2; r++)
        #pragma unroll
        for (int c = 0; c < 2; c++) {
            int m = m0 + ty + r * 32;
            int n = n0 + tx + c * 8;
            g_xh[(size_t)m * 1024 + n] = aH[r][c] + bh[n];
            g_xt[(size_t)m * 1024 + n] = aT[r][c] + bt[n];
        }
}

// ---------------------------------------------------------------------------
// One highway phase (device function inside the persistent kernel):
//   h = tanh(addH + s@Wh);  g = sigmoid(addT + s@Wt);  s' = (h - s)*g + s
// CTA tile [64m x 16n x 2 gates]; this CTA: n0 = (bid&63)*16, m0 = (bid>>6)*64.
// State loads use __ldcg (L1-bypass) for cross-CTA coherence.
// ---------------------------------------------------------------------------
static __device__ void phase_step(
    const float* __restrict__ A, float* __restrict__ dst,
    const float* __restrict__ Wh, const float* __restrict__ Wt,
    const float* __restrict__ addH, const float* __restrict__ addT, int l0,
    float* sA, float* sWh, float* sWt)
{
    const int tid = threadIdx.x;
    const int tx  = tid & 7;
    const int ty  = tid >> 3;
    const int n0  = (blockIdx.x & 63) * 16;
    const int m0  = (blockIdx.x >> 6) * 64;

    const int sm  = tid >> 3;
    const int sk4 = (tid & 7) * 4;
    const int wn  = tid & 15;
    const int wk  = tid >> 4;

    float aH[2][2] = {{0.f,0.f},{0.f,0.f}};
    float aT[2][2] = {{0.f,0.f},{0.f,0.f}};

    // stage 0
    *(float4*)&sA[ sm       * 36 + sk4] =
        __ldcg((const float4*)&A[(size_t)(m0 + sm     ) * 1024 + sk4]);
    *(float4*)&sA[(sm + 32) * 36 + sk4] =
        __ldcg((const float4*)&A[(size_t)(m0 + sm + 32) * 1024 + sk4]);
    sWh[wn * 36 + wk     ] = Wh[(size_t) wk       * 1024 + n0 + wn];
    sWh[wn * 36 + wk + 16] = Wh[(size_t)(wk + 16) * 1024 + n0 + wn];
    sWt[wn * 36 + wk     ] = Wt[(size_t) wk       * 1024 + n0 + wn];
    sWt[wn * 36 + wk + 16] = Wt[(size_t)(wk + 16) * 1024 + n0 + wn];
    __syncthreads();

    for (int st = 0; st < 32; st++) {
        const int cur = st & 1;
        float4 pA0, pA1; float pWh0, pWh1, pWt0, pWt1;
        if (st < 31) {
            int k0 = (st + 1) * 32;
            pA0 = __ldcg((const float4*)&A[(size_t)(m0 + sm     ) * 1024 + k0 + sk4]);
            pA1 = __ldcg((const float4*)&A[(size_t)(m0 + sm + 32) * 1024 + k0 + sk4]);
            pWh0 = Wh[(size_t)(k0 + wk     ) * 1024 + n0 + wn];
            pWh1 = Wh[(size_t)(k0 + wk + 16) * 1024 + n0 + wn];
            pWt0 = Wt[(size_t)(k0 + wk     ) * 1024 + n0 + wn];
            pWt1 = Wt[(size_t)(k0 + wk + 16) * 1024 + n0 + wn];
        }
        const float* cA  = sA  + cur * 2304;
        const float* cWh = sWh + cur * 576;
        const float* cWt = sWt + cur * 576;
        #pragma unroll
        for (int k4 = 0; k4 < 8; k4++) {
            float4 a0 = *(const float4*)&cA [ ty       * 36 + k4 * 4];
            float4 a1 = *(const float4*)&cA [(ty + 32) * 36 + k4 * 4];
            float4 h0 = *(const float4*)&cWh[ tx       * 36 + k4 * 4];
            float4 h1 = *(const float4*)&cWh[(tx + 8 ) * 36 + k4 * 4];
            float4 q0 = *(const float4*)&cWt[ tx       * 36 + k4 * 4];
            float4 q1 = *(const float4*)&cWt[(tx + 8 ) * 36 + k4 * 4];
            acc4(aH[0][0], a0, h0); acc4(aH[0][1], a0, h1);
            acc4(aH[1][0], a1, h0); acc4(aH[1][1], a1, h1);
            acc4(aT[0][0], a0, q0); acc4(aT[0][1], a0, q1);
            acc4(aT[1][0], a1, q0); acc4(aT[1][1], a1, q1);
        }
        if (st < 31) {
            float* nA  = sA  + (cur ^ 1) * 2304;
            float* nWh = sWh + (cur ^ 1) * 576;
            float* nWt = sWt + (cur ^ 1) * 576;
            *(float4*)&nA[ sm       * 36 + sk4] = pA0;
            *(float4*)&nA[(sm + 32) * 36 + sk4] = pA1;
            nWh[wn * 36 + wk     ] = pWh0;
            nWh[wn * 36 + wk + 16] = pWh1;
            nWt[wn * 36 + wk     ] = pWt0;
            nWt[wn * 36 + wk + 16] = pWt1;
        }
        __syncthreads();
    }

    #pragma unroll
    for (int r = 0; r < 2; r++)
        #pragma unroll
        for (int c = 0; c < 2; c++) {
            int m = m0 + ty + r * 32;
            int n = n0 + tx + c * 8;
            size_t off = (size_t)m * 1024 + n;
            float addh = l0 ? addH[off] : addH[n];
            float addt = l0 ? addT[off] : addT[n];
            float so   = __ldcg(&A[off]);
            float hh   = tanhf(addh + aH[r][c]);
            float gg   = 1.f / (1.f + expf(-(addt + aT[r][c])));
            dst[off]   = (hh - so) * gg + so;
        }
}

// ---------------------------------------------------------------------------
// Projection (device function): out[(b*T + t)*256 + n] = S[b,:]@Wp[:,n] + bp[n]
// This CTA: rows m0..m0+63 (m0 = (bid>>6)*64), cols n0..n0+3 (n0 = (bid&63)*4).
// Runs inside the barrier interval after phase 2 (reads only the same state
// buffer the next phase 0 reads). Reuses sA (>=4352 floats) and sWh (>=256).
// ---------------------------------------------------------------------------
static __device__ void proj_step(const float* __restrict__ A,
                                 const float* __restrict__ Wp,
                                 const float* __restrict__ bp,
                                 float* __restrict__ out, int t,
                                 float* sAf, float* sWp)
{
    const int tid = threadIdx.x;
    const int m0  = (blockIdx.x >> 6) * 64;
    const int n0  = (blockIdx.x & 63) * 4;
    const int rt  = tid & 63;          // output row within tile
    const int ct  = tid >> 6;          // output col 0..3
    const int sr  = tid >> 2;          // staging row 0..63
    const int sc  = (tid & 3) * 16;    // staging k-offset
    float acc = 0.f;

    for (int k0 = 0; k0 < 1024; k0 += 64) {
        #pragma unroll
        for (int i = 0; i < 4; i++)
            *(float4*)&sAf[sr * 68 + sc + i * 4] =
                __ldcg((const float4*)&A[(size_t)(m0 + sr) * 1024 + k0 + sc + i * 4]);
        if (tid < 64)
            *(float4*)&sWp[tid * 4] =
                *(const float4*)&Wp[(size_t)(k0 + tid) * 256 + n0];
        __syncthreads();
        #pragma unroll
        for (int k4 = 0; k4 < 16; k4++) {
            float4 a = *(const float4*)&sAf[rt * 68 + k4 * 4];
            acc += a.x * sWp[(k4 * 4 + 0) * 4 + ct];
            acc += a.y * sWp[(k4 * 4 + 1) * 4 + ct];
            acc += a.z * sWp[(k4 * 4 + 2) * 4 + ct];
            acc += a.w * sWp[(k4 * 4 + 3) * 4 + ct];
        }
        __syncthreads();
    }
    out[((size_t)(m0 + rt) * 256 + t) * 256 + n0 + ct] = acc + bp[n0 + ct];
}

// ---------------------------------------------------------------------------
// Persistent recurrence kernel: 128 CTAs (co-resident), 3 grid barriers/step.
// Collapses the former 1024 graph nodes into 1.
// ---------------------------------------------------------------------------
__global__ __launch_bounds__(256) void recurrence_kernel(
    const float* __restrict__ Wh0s, const float* __restrict__ Wt0s,
    const float* __restrict__ Whh,  const float* __restrict__ Wth,
    const float* __restrict__ bhh,  const float* __restrict__ bth,
    const float* __restrict__ Wp,   const float* __restrict__ bp,
    float* __restrict__ out)
{
    __shared__ float sA [2 * 2304];
    __shared__ float sWh[2 * 576];
    __shared__ float sWt[2 * 576];

    int p = 0;
    for (int t = 0; t < Tc; t++) {
        // layer 0 (input-dependent adds)
        phase_step(g_s[p], g_s[p ^ 1], Wh0s, Wt0s,
                   g_xh + (size_t)t * Bc * Rc, g_xt + (size_t)t * Bc * Rc, 1,
                   sA, sWh, sWt);
        p ^= 1; gbar();
        // layer 1
        phase_step(g_s[p], g_s[p ^ 1], Whh, Wth, bhh, bth, 0, sA, sWh, sWt);
        p ^= 1; gbar();
        // layer 2
        phase_step(g_s[p], g_s[p ^ 1], Whh + 1024 * 1024, Wth + 1024 * 1024,
                   bhh + 1024, bth + 1024, 0, sA, sWh, sWt);
        p ^= 1; gbar();
        // projection of S_t: shares the barrier interval with next phase 0
        // (both only READ g_s[p]; the gbar after next phase 0 orders proj
        //  before phase 1 overwrites any buffer proj reads).
        proj_step(g_s[p], Wp, bp, out, t, sA, sWh);
        __syncthreads();   // smem handoff back to phase 0 staging
    }
}

// ---------------------------------------------------------------------------
// Host launcher (graph-capturable: 4 kernel launches total)
// ---------------------------------------------------------------------------
extern "C" void kernel_launch(void* const* d_in, const int* in_sizes, int n_in,
                              void* d_out, int out_size) {
    const int*   ids  = (const int*)  d_in[0];
    const float* emb  = (const float*)d_in[1];
    const float* Wh0x = (const float*)d_in[2];
    const float* Wh0s = (const float*)d_in[3];
    const float* bh0  = (const float*)d_in[4];
    const float* Wt0x = (const float*)d_in[5];
    const float* Wt0s = (const float*)d_in[6];
    const float* bt0  = (const float*)d_in[7];
    const float* Whh  = (const float*)d_in[8];    // [2,1024,1024]
    const float* bhh  = (const float*)d_in[9];    // [2,1024]
    const float* Wth  = (const float*)d_in[10];
    const float* bth  = (const float*)d_in[11];
    const float* Wp   = (const float*)d_in[12];   // [1024,256]
    const float* bp   = (const float*)d_in[13];
    float* out = (float*)d_out;

    zero_kernel  <<<128, 256>>>();
    gather_kernel<<<8192, 256>>>(ids, emb);
    prologue_kernel<<<dim3(64, 512), 256>>>(Wh0x, Wt0x, bh0, bt0);
    recurrence_kernel<<<128, 256>>>(Wh0s, Wt0s, Whh, Wth, bhh, bth, Wp, bp, out);
}